// round 2
// baseline (speedup 1.0000x reference)
#include <cuda_runtime.h>
#include <math.h>

#define NN 2048      // nodes
#define NB 64        // batch
#define FU 64        // units == in_dim
#define CXH 8192     // 2*NB*FU  (x|h packed columns)
#define C1  4096     // NB*FU

// ---------------- scratch (__device__ globals; no allocation allowed) ----------------
__device__ float g_dinv[NN];
__device__ float g_adjT[(size_t)NN * NN];
__device__ float g_XH [(size_t)NN * CXH];   // [m][c], c = b*64+f (x), 4096 + b*64+f (h)
__device__ float g_A1 [(size_t)NN * CXH];   // adjT @ XH
__device__ float g_A2 [(size_t)NN * CXH];   // 2*adjT@A1 - XH
__device__ float g_RH [(size_t)NN * C1];    // r * h
__device__ float g_AR1[(size_t)NN * C1];
__device__ float g_AR2[(size_t)NN * C1];
__device__ float g_U  [(size_t)NN * C1];    // update gate
__device__ float g_Wru[384 * 128];          // permuted: row = s*64+f
__device__ float g_Wc [384 * 64];

// ---------------- d_inv = 1 / (rowsum(adj) + 1) ----------------
__global__ void rowsum_kernel(const float* __restrict__ adj) {
    int m = blockIdx.x;
    const float* row = adj + (size_t)m * NN;
    float s = 0.f;
    for (int i = threadIdx.x; i < NN; i += 256) s += row[i];
    #pragma unroll
    for (int o = 16; o; o >>= 1) s += __shfl_down_sync(0xffffffffu, s, o);
    __shared__ float sm[8];
    if ((threadIdx.x & 31) == 0) sm[threadIdx.x >> 5] = s;
    __syncthreads();
    if (threadIdx.x < 8) {
        float v = sm[threadIdx.x];
        #pragma unroll
        for (int o = 4; o; o >>= 1) v += __shfl_down_sync(0xffu, v, o);
        if (threadIdx.x == 0) g_dinv[m] = 1.0f / (v + 1.0f);
    }
}

// ---------------- adjT[n][m] = (adj[m][n] + (m==n)) * dinv[m] ----------------
__global__ void build_adjT(const float* __restrict__ adj) {
    __shared__ float tile[32][33];
    int mb = blockIdx.y * 32, nb = blockIdx.x * 32;
    int tx = threadIdx.x, ty = threadIdx.y;   // 32 x 8
    #pragma unroll
    for (int i = 0; i < 32; i += 8) {
        int m = mb + ty + i, n = nb + tx;
        float v = adj[(size_t)m * NN + n];
        if (m == n) v += 1.0f;
        tile[ty + i][tx] = v * g_dinv[m];
    }
    __syncthreads();
    #pragma unroll
    for (int i = 0; i < 32; i += 8) {
        int n = nb + ty + i, m = mb + tx;
        g_adjT[(size_t)n * NN + m] = tile[tx][ty + i];
    }
}

// ---------------- pack x,h -> XH [m][c] ----------------
__global__ void pack_XH(const float* __restrict__ x, const float* __restrict__ h) {
    int idx4 = blockIdx.x * 256 + threadIdx.x;   // float4 index, total 2048*8192/4
    int m  = idx4 >> 11;                         // 2048 float4 per row
    int c  = (idx4 & 2047) * 4;
    const float* src;
    if (c < C1) { int b = c >> 6, f = c & 63; src = x + (size_t)b * (NN * 64) + m * 64 + f; }
    else { int cc = c - C1; int b = cc >> 6, f = cc & 63; src = h + (size_t)b * (NN * 64) + m * 64 + f; }
    *(float4*)&g_XH[(size_t)m * CXH + c] = *(const float4*)src;
}

// ---------------- permute W rows: row(s,f) -> s*64+f ----------------
// s<3: x-part k=s  -> src row f*3+s ; s>=3: h/rh-part -> 192 + f*3 + (s-3)
__global__ void permW(const float* __restrict__ Wru, const float* __restrict__ Wc) {
    int tid = blockIdx.x * 256 + threadIdx.x;
    if (tid < 384 * 128) {
        int row = tid >> 7, o = tid & 127;
        int s = row >> 6, f = row & 63;
        int src = (s < 3) ? (f * 3 + s) : (192 + f * 3 + (s - 3));
        g_Wru[row * 128 + o] = Wru[src * 128 + o];
    }
    if (tid < 384 * 64) {
        int row = tid >> 6, o = tid & 63;
        int s = row >> 6, f = row & 63;
        int src = (s < 3) ? (f * 3 + s) : (192 + f * 3 + (s - 3));
        g_Wc[row * 64 + o] = Wc[src * 64 + o];
    }
}

// ---------------- SGEMM: C = alpha * (adjT @ B) [+ beta * Cin] ----------------
// A: [2048][2048] row-major, B/C: [2048][Ncols] row-major. 128x128 tile, BK=8.
__global__ __launch_bounds__(256, 2)
void sgemm128(const float* __restrict__ Amat, const float* __restrict__ Bmat,
              const float* __restrict__ Cin, float* __restrict__ Cout,
              int Ncols, float alpha, float beta) {
    __shared__ float As[8][128];
    __shared__ float Bs[8][128];
    int t  = threadIdx.x;
    int tx = t & 15, ty = t >> 4;
    int m0 = blockIdx.y * 128, n0 = blockIdx.x * 128;

    float acc[8][8] = {};
    int ar = t >> 1, ac = (t & 1) * 4;        // A tile load: 128 rows x 8 cols
    int br = t >> 5, bc = (t & 31) * 4;       // B tile load: 8 rows x 128 cols
    const float* Aptr = Amat + (size_t)(m0 + ar) * NN + ac;
    const float* Bptr = Bmat + (size_t)br * Ncols + n0 + bc;

    for (int kt = 0; kt < NN; kt += 8) {
        float4 av = *(const float4*)(Aptr + kt);
        float4 bv = *(const float4*)(Bptr + (size_t)kt * Ncols);
        __syncthreads();
        As[ac + 0][ar] = av.x; As[ac + 1][ar] = av.y;
        As[ac + 2][ar] = av.z; As[ac + 3][ar] = av.w;
        *(float4*)&Bs[br][bc] = bv;
        __syncthreads();
        #pragma unroll
        for (int k = 0; k < 8; ++k) {
            float4 a0 = *(float4*)&As[k][ty * 8];
            float4 a1 = *(float4*)&As[k][ty * 8 + 4];
            float4 b0 = *(float4*)&Bs[k][tx * 8];
            float4 b1 = *(float4*)&Bs[k][tx * 8 + 4];
            float a[8] = {a0.x, a0.y, a0.z, a0.w, a1.x, a1.y, a1.z, a1.w};
            float b[8] = {b0.x, b0.y, b0.z, b0.w, b1.x, b1.y, b1.z, b1.w};
            #pragma unroll
            for (int i = 0; i < 8; ++i)
                #pragma unroll
                for (int j = 0; j < 8; ++j)
                    acc[i][j] += a[i] * b[j];
        }
    }
    #pragma unroll
    for (int i = 0; i < 8; ++i) {
        int m = m0 + ty * 8 + i;
        size_t base = (size_t)m * Ncols + n0 + tx * 8;
        float v[8];
        #pragma unroll
        for (int j = 0; j < 8; ++j) v[j] = alpha * acc[i][j];
        if (Cin) {
            float4 c0 = *(const float4*)&Cin[base];
            float4 c1 = *(const float4*)&Cin[base + 4];
            v[0] += beta * c0.x; v[1] += beta * c0.y; v[2] += beta * c0.z; v[3] += beta * c0.w;
            v[4] += beta * c1.x; v[5] += beta * c1.y; v[6] += beta * c1.z; v[7] += beta * c1.w;
        }
        float4 o0 = {v[0], v[1], v[2], v[3]};
        float4 o1 = {v[4], v[5], v[6], v[7]};
        *(float4*)&Cout[base] = o0;
        *(float4*)&Cout[base + 4] = o1;
    }
}

// ---------------- projection RU: ru = sigmoid(F @ Wru + b); emit U and RH ----------------
// one block per m; 64 nodes (b) x 128 outputs; K=384 in 12 chunks of 32
__global__ __launch_bounds__(256)
void proj_ru(const float* __restrict__ b_ru) {
    int m = blockIdx.x;
    __shared__ float Fs[64][32];
    __shared__ float Ws[32][128];
    int t  = threadIdx.x;
    int nb = (t >> 5) * 8;        // 8 nodes per thread (same for whole warp -> LDS broadcast)
    int oc = (t & 31) * 4;        // 4 output cols
    float acc[8][4] = {};

    for (int ch = 0; ch < 12; ++ch) {
        int k0 = ch * 32;
        int s = k0 >> 6, f0 = k0 & 63;
        const float* base;
        switch (s) {
            case 0: base = g_XH; break; case 1: base = g_A1; break; case 2: base = g_A2; break;
            case 3: base = g_XH; break; case 4: base = g_A1; break; default: base = g_A2; break;
        }
        const float* src = base + (size_t)m * CXH + (s >= 3 ? C1 : 0) + f0;
        __syncthreads();
        for (int q = t; q < 512; q += 256) {               // Fs: 64x32
            int node = q >> 3, j4 = (q & 7) * 4;
            *(float4*)&Fs[node][j4] = *(const float4*)(src + node * 64 + j4);
        }
        for (int q = t; q < 1024; q += 256) {              // Ws: 32x128
            int row = q >> 5, c4 = (q & 31) * 4;
            *(float4*)&Ws[row][c4] = *(const float4*)&g_Wru[(k0 + row) * 128 + c4];
        }
        __syncthreads();
        #pragma unroll
        for (int kk = 0; kk < 32; ++kk) {
            float4 w = *(float4*)&Ws[kk][oc];
            #pragma unroll
            for (int i = 0; i < 8; ++i) {
                float fv = Fs[nb + i][kk];
                acc[i][0] += fv * w.x; acc[i][1] += fv * w.y;
                acc[i][2] += fv * w.z; acc[i][3] += fv * w.w;
            }
        }
    }
    float bias[4] = {b_ru[oc], b_ru[oc + 1], b_ru[oc + 2], b_ru[oc + 3]};
    #pragma unroll
    for (int i = 0; i < 8; ++i) {
        int b = nb + i;
        #pragma unroll
        for (int j = 0; j < 4; ++j) {
            int o = oc + j;
            float v = 1.0f / (1.0f + expf(-(acc[i][j] + bias[j])));
            if (o < 64) {
                float h = g_XH[(size_t)m * CXH + C1 + b * 64 + o];
                g_RH[(size_t)m * C1 + b * 64 + o] = v * h;
            } else {
                g_U[(size_t)m * C1 + b * 64 + (o - 64)] = v;
            }
        }
    }
}

// ---------------- projection C + GRU combine -> output ----------------
__global__ __launch_bounds__(256)
void proj_c(const float* __restrict__ b_c, float* __restrict__ out) {
    int m = blockIdx.x;
    __shared__ float Fs[64][32];
    __shared__ float Ws[32][64];
    int t  = threadIdx.x;
    int nb = (t >> 5) * 8;
    int oc = (t & 31) * 2;
    float acc[8][2] = {};

    for (int ch = 0; ch < 12; ++ch) {
        int k0 = ch * 32;
        int s = k0 >> 6, f0 = k0 & 63;
        const float* src;
        switch (s) {
            case 0: src = g_XH  + (size_t)m * CXH; break;
            case 1: src = g_A1  + (size_t)m * CXH; break;
            case 2: src = g_A2  + (size_t)m * CXH; break;
            case 3: src = g_RH  + (size_t)m * C1;  break;
            case 4: src = g_AR1 + (size_t)m * C1;  break;
            default: src = g_AR2 + (size_t)m * C1; break;
        }
        src += f0;
        __syncthreads();
        for (int q = t; q < 512; q += 256) {
            int node = q >> 3, j4 = (q & 7) * 4;
            *(float4*)&Fs[node][j4] = *(const float4*)(src + node * 64 + j4);
        }
        for (int q = t; q < 512; q += 256) {
            int row = q >> 4, c4 = (q & 15) * 4;
            *(float4*)&Ws[row][c4] = *(const float4*)&g_Wc[(k0 + row) * 64 + c4];
        }
        __syncthreads();
        #pragma unroll
        for (int kk = 0; kk < 32; ++kk) {
            float2 w = *(float2*)&Ws[kk][oc];
            #pragma unroll
            for (int i = 0; i < 8; ++i) {
                float fv = Fs[nb + i][kk];
                acc[i][0] += fv * w.x; acc[i][1] += fv * w.y;
            }
        }
    }
    float bias[2] = {b_c[oc], b_c[oc + 1]};
    #pragma unroll
    for (int i = 0; i < 8; ++i) {
        int b = nb + i;
        #pragma unroll
        for (int j = 0; j < 2; ++j) {
            int o = oc + j;
            float c = tanhf(acc[i][j] + bias[j]);
            float u = g_U[(size_t)m * C1 + b * 64 + o];
            float h = g_XH[(size_t)m * CXH + C1 + b * 64 + o];
            out[(size_t)b * (NN * 64) + m * 64 + o] = u * h + (1.0f - u) * c;
        }
    }
}

// ---------------- launch ----------------
extern "C" void kernel_launch(void* const* d_in, const int* in_sizes, int n_in,
                              void* d_out, int out_size) {
    const float* inputs = (const float*)d_in[0];
    const float* hx     = (const float*)d_in[1];
    const float* adj    = (const float*)d_in[2];
    const float* W_ru   = (const float*)d_in[3];
    const float* b_ru   = (const float*)d_in[4];
    const float* W_c    = (const float*)d_in[5];
    const float* b_c    = (const float*)d_in[6];
    float* out = (float*)d_out;

    float *p_adjT, *p_XH, *p_A1, *p_A2, *p_RH, *p_AR1, *p_AR2;
    cudaGetSymbolAddress((void**)&p_adjT, g_adjT);
    cudaGetSymbolAddress((void**)&p_XH,  g_XH);
    cudaGetSymbolAddress((void**)&p_A1,  g_A1);
    cudaGetSymbolAddress((void**)&p_A2,  g_A2);
    cudaGetSymbolAddress((void**)&p_RH,  g_RH);
    cudaGetSymbolAddress((void**)&p_AR1, g_AR1);
    cudaGetSymbolAddress((void**)&p_AR2, g_AR2);

    rowsum_kernel<<<NN, 256>>>(adj);
    build_adjT<<<dim3(NN / 32, NN / 32), dim3(32, 8)>>>(adj);
    pack_XH<<<(NN * CXH / 4) / 256, 256>>>(inputs, hx);
    permW<<<(384 * 128 + 255) / 256, 256>>>(W_ru, W_c);

    // A1 = adjT @ XH ; A2 = 2*adjT@A1 - XH
    sgemm128<<<dim3(CXH / 128, NN / 128), 256>>>(p_adjT, p_XH, nullptr, p_A1, CXH, 1.0f, 0.0f);
    sgemm128<<<dim3(CXH / 128, NN / 128), 256>>>(p_adjT, p_A1, p_XH,   p_A2, CXH, 2.0f, -1.0f);

    // ru -> U, RH
    proj_ru<<<NN, 256>>>(b_ru);

    // AR1 = adjT @ RH ; AR2 = 2*adjT@AR1 - RH
    sgemm128<<<dim3(C1 / 128, NN / 128), 256>>>(p_adjT, p_RH,  nullptr, p_AR1, C1, 1.0f, 0.0f);
    sgemm128<<<dim3(C1 / 128, NN / 128), 256>>>(p_adjT, p_AR1, p_RH,   p_AR2, C1, 2.0f, -1.0f);

    // c projection + GRU combine -> out
    proj_c<<<NN, 256>>>(b_c, out);
}

// round 4
// speedup vs baseline: 2.5414x; 2.5414x over previous
#include <cuda_runtime.h>
#include <cuda_bf16.h>
#include <math.h>
#include <stdint.h>

#define NN 2048      // nodes
#define CXH 8192     // 2*64*64 columns of [x|h]
#define C1  4096     // 64*64
#define KTOT 6144    // 3 * NN (split-bf16 K concatenation)

// ---------------- device scratch ----------------
__device__ float g_dinv[NN];
__device__ float g_XH [(size_t)NN * CXH];
__device__ float g_A1 [(size_t)NN * CXH];
__device__ float g_A2 [(size_t)NN * CXH];
__device__ float g_RH [(size_t)NN * C1];
__device__ float g_AR1[(size_t)NN * C1];
__device__ float g_AR2[(size_t)NN * C1];
__device__ float g_U  [(size_t)NN * C1];
__device__ float g_Wru[384 * 128];
__device__ float g_Wc [384 * 64];
__device__ __nv_bfloat16 g_Asp[(size_t)NN * KTOT];    // A' = [Ahi|Ahi|Alo]
__device__ __nv_bfloat16 g_B1 [(size_t)CXH * KTOT];   // split(XH)^T   [hi|lo|hi]
__device__ __nv_bfloat16 g_B2 [(size_t)CXH * KTOT];   // split(A1)^T
__device__ __nv_bfloat16 g_B3 [(size_t)C1  * KTOT];   // split(RH)^T
__device__ __nv_bfloat16 g_B4 [(size_t)C1  * KTOT];   // split(AR1)^T

// ---------------- helpers ----------------
__device__ __forceinline__ uint32_t smem_u32(const void* p) {
    uint32_t a;
    asm("{ .reg .u64 t; cvta.to.shared.u64 t, %1; cvt.u32.u64 %0, t; }" : "=r"(a) : "l"(p));
    return a;
}
__device__ __forceinline__ void cpasync16(uint32_t dst, const void* src) {
    asm volatile("cp.async.cg.shared.global [%0], [%1], 16;" :: "r"(dst), "l"(src));
}
__device__ __forceinline__ void ldsm4(uint32_t* r, uint32_t addr) {
    asm volatile("ldmatrix.sync.aligned.m8n8.x4.shared.b16 {%0,%1,%2,%3}, [%4];"
        : "=r"(r[0]), "=r"(r[1]), "=r"(r[2]), "=r"(r[3]) : "r"(addr));
}
__device__ __forceinline__ void mma16816(float* d, const uint32_t* a, const uint32_t* b) {
    asm volatile("mma.sync.aligned.m16n8k16.row.col.f32.bf16.bf16.f32 "
        "{%0,%1,%2,%3}, {%4,%5,%6,%7}, {%8,%9}, {%0,%1,%2,%3};"
        : "+f"(d[0]), "+f"(d[1]), "+f"(d[2]), "+f"(d[3])
        : "r"(a[0]), "r"(a[1]), "r"(a[2]), "r"(a[3]), "r"(b[0]), "r"(b[1]));
}

// ---------------- small prep kernels ----------------
__global__ void rowsum_kernel(const float* __restrict__ adj) {
    int m = blockIdx.x;
    const float* row = adj + (size_t)m * NN;
    float s = 0.f;
    for (int i = threadIdx.x; i < NN; i += 256) s += row[i];
    #pragma unroll
    for (int o = 16; o; o >>= 1) s += __shfl_down_sync(0xffffffffu, s, o);
    __shared__ float sm[8];
    if ((threadIdx.x & 31) == 0) sm[threadIdx.x >> 5] = s;
    __syncthreads();
    if (threadIdx.x < 8) {
        float v = sm[threadIdx.x];
        #pragma unroll
        for (int o = 4; o; o >>= 1) v += __shfl_down_sync(0xffu, v, o);
        if (threadIdx.x == 0) g_dinv[m] = 1.0f / (v + 1.0f);
    }
}

__global__ void pack_XH(const float* __restrict__ x, const float* __restrict__ h) {
    int idx4 = blockIdx.x * 256 + threadIdx.x;
    int m = idx4 >> 11;
    int c = (idx4 & 2047) * 4;
    const float* src;
    if (c < C1) { int b = c >> 6, f = c & 63; src = x + (size_t)b * (NN * 64) + m * 64 + f; }
    else { int cc = c - C1; int b = cc >> 6, f = cc & 63; src = h + (size_t)b * (NN * 64) + m * 64 + f; }
    *(float4*)&g_XH[(size_t)m * CXH + c] = *(const float4*)src;
}

__global__ void permW(const float* __restrict__ Wru, const float* __restrict__ Wc) {
    int tid = blockIdx.x * 256 + threadIdx.x;
    if (tid < 384 * 128) {
        int row = tid >> 7, o = tid & 127;
        int s = row >> 6, f = row & 63;
        int src = (s < 3) ? (f * 3 + s) : (192 + f * 3 + (s - 3));
        g_Wru[row * 128 + o] = Wru[src * 128 + o];
    }
    if (tid < 384 * 64) {
        int row = tid >> 6, o = tid & 63;
        int s = row >> 6, f = row & 63;
        int src = (s < 3) ? (f * 3 + s) : (192 + f * 3 + (s - 3));
        g_Wc[row * 64 + o] = Wc[src * 64 + o];
    }
}

// A'[m][k'] from adj: adjT[m][k] = (adj[k][m] + (k==m)) * dinv[k]; segs [hi|hi|lo]
__global__ void buildA_split(const float* __restrict__ adj) {
    __shared__ float tile[64][65];
    __shared__ float sdinv[64];
    int k0 = blockIdx.y * 64, m0 = blockIdx.x * 64;
    int t = threadIdx.x;
    if (t < 64) sdinv[t] = g_dinv[k0 + t];
    #pragma unroll
    for (int i = 0; i < 16; i++) {
        int q = t + 256 * i; int r = q >> 6, c = q & 63;
        tile[r][c] = adj[(size_t)(k0 + r) * NN + m0 + c];
    }
    __syncthreads();
    #pragma unroll
    for (int i = 0; i < 16; i++) {
        int q = t + 256 * i; int f = q >> 6, n = q & 63;
        int kk = k0 + n, mm = m0 + f;
        float v = tile[n][f];
        if (kk == mm) v += 1.0f;
        v *= sdinv[n];
        __nv_bfloat16 hi = __float2bfloat16(v);
        __nv_bfloat16 lo = __float2bfloat16(v - __bfloat162float(hi));
        size_t base = (size_t)mm * KTOT + kk;
        g_Asp[base] = hi; g_Asp[base + NN] = hi; g_Asp[base + 2 * NN] = lo;
    }
}

// B'[c][k'] = split of src[k][c]; segs [hi|lo|hi]
__global__ void split_T(const float* __restrict__ src, __nv_bfloat16* __restrict__ dst, int Ncols) {
    __shared__ float tile[64][65];
    int k0 = blockIdx.y * 64, c0 = blockIdx.x * 64;
    int t = threadIdx.x;
    #pragma unroll
    for (int i = 0; i < 16; i++) {
        int q = t + 256 * i; int r = q >> 6, c = q & 63;
        tile[r][c] = src[(size_t)(k0 + r) * Ncols + c0 + c];
    }
    __syncthreads();
    #pragma unroll
    for (int i = 0; i < 16; i++) {
        int q = t + 256 * i; int f = q >> 6, n = q & 63;
        float v = tile[n][f];
        __nv_bfloat16 hi = __float2bfloat16(v);
        __nv_bfloat16 lo = __float2bfloat16(v - __bfloat162float(hi));
        size_t base = (size_t)(c0 + f) * KTOT + (k0 + n);
        dst[base] = hi; dst[base + NN] = lo; dst[base + 2 * NN] = hi;
    }
}

// ---------------- HMMA GEMM: Cout = alpha*(A' @ B'^T) + beta*Cin ----------------
// A': [2048][KTOT] bf16 row-major; B': [Ncols][KTOT] bf16 row-major (k contiguous).
// CTA tile 128(M) x 256(N), BK=32, 512 threads (16 warps, warp tile 64x32).
// smem rows: 32 bf16 + pad -> 40 elems (80 B), conflict-free ldmatrix.
#define ROWB 80
#define ASZ  (128 * ROWB)
#define BSZ  (256 * ROWB)
#define STB  (ASZ + BSZ)          // 30720 B per stage
#define GSMEM (4 * STB)           // 122880 B, 4-slot ring
#define NST  (KTOT / 32)          // 192

__global__ __launch_bounds__(512, 1)
void gemm_mma(const __nv_bfloat16* __restrict__ A, const __nv_bfloat16* __restrict__ B,
              const float* __restrict__ Cin, float* __restrict__ Cout,
              int Ncols, float alpha, float beta) {
    extern __shared__ char smem[];
    uint32_t sbase = smem_u32(smem);
    int t = threadIdx.x;
    int lane = t & 31, wid = t >> 5;
    int m0 = blockIdx.y * 128;
    int n0 = blockIdx.x * 256;
    int wm = (wid & 1) * 64;
    int wn = (wid >> 1) * 32;

    // per-thread ldmatrix offsets (lane-invariant parts precomputed)
    uint32_t aOff[4], bOff[2];
    #pragma unroll
    for (int mt = 0; mt < 4; mt++)
        aOff[mt] = (uint32_t)((wm + mt * 16 + (lane & 15)) * ROWB + (lane >> 4) * 16);
    #pragma unroll
    for (int np = 0; np < 2; np++)
        bOff[np] = (uint32_t)(ASZ + (wn + np * 16 + (lane & 7) + ((lane >> 4) << 3)) * ROWB
                              + ((lane >> 3) & 1) * 16);

    auto load_stage = [&](int s) {
        int slot = s & 3; int k0 = s * 32;
        uint32_t ab = sbase + slot * STB;
        const __nv_bfloat16* gA = A + (size_t)m0 * KTOT + k0;
        const __nv_bfloat16* gB = B + (size_t)n0 * KTOT + k0;
        #pragma unroll
        for (int i = 0; i < 3; i++) {
            int q = t + 512 * i;
            if (q < 512) {
                int r = q >> 2, c4 = q & 3;
                cpasync16(ab + r * ROWB + c4 * 16, gA + (size_t)r * KTOT + c4 * 8);
            } else {
                int qq = q - 512; int r = qq >> 2, c4 = qq & 3;
                cpasync16(ab + ASZ + r * ROWB + c4 * 16, gB + (size_t)r * KTOT + c4 * 8);
            }
        }
        asm volatile("cp.async.commit_group;" ::: "memory");
    };

    float acc[4][4][4] = {};

    load_stage(0); load_stage(1); load_stage(2);

    for (int s = 0; s < NST; ++s) {
        if (s <= NST - 3)      asm volatile("cp.async.wait_group 2;" ::: "memory");
        else if (s == NST - 2) asm volatile("cp.async.wait_group 1;" ::: "memory");
        else                   asm volatile("cp.async.wait_group 0;" ::: "memory");
        __syncthreads();

        uint32_t sb = sbase + (s & 3) * STB;
        #pragma unroll
        for (int k16 = 0; k16 < 2; k16++) {
            uint32_t a[4][4], b[2][4];
            #pragma unroll
            for (int mt = 0; mt < 4; mt++) ldsm4(a[mt], sb + aOff[mt] + k16 * 32);
            #pragma unroll
            for (int np = 0; np < 2; np++) ldsm4(b[np], sb + bOff[np] + k16 * 32);
            #pragma unroll
            for (int mt = 0; mt < 4; mt++)
                #pragma unroll
                for (int nt = 0; nt < 4; nt++)
                    mma16816(acc[mt][nt], a[mt], &b[nt >> 1][(nt & 1) * 2]);
        }

        if (s + 3 < NST) load_stage(s + 3);
    }

    // epilogue: direct global stores, alpha/beta fused
    bool has_cin = (Cin != nullptr);
    #pragma unroll
    for (int mt = 0; mt < 4; mt++) {
        #pragma unroll
        for (int nt = 0; nt < 4; nt++) {
            int m = m0 + wm + mt * 16 + (lane >> 2);
            int n = n0 + wn + nt * 8 + (lane & 3) * 2;
            size_t g0 = (size_t)m * Ncols + n;
            size_t g1 = g0 + (size_t)8 * Ncols;
            float v0 = alpha * acc[mt][nt][0], v1 = alpha * acc[mt][nt][1];
            float v2 = alpha * acc[mt][nt][2], v3 = alpha * acc[mt][nt][3];
            if (has_cin) {
                float2 c0 = *(const float2*)&Cin[g0];
                float2 c1 = *(const float2*)&Cin[g1];
                v0 += beta * c0.x; v1 += beta * c0.y;
                v2 += beta * c1.x; v3 += beta * c1.y;
            }
            float2 o0 = {v0, v1}, o1 = {v2, v3};
            *(float2*)&Cout[g0] = o0;
            *(float2*)&Cout[g1] = o1;
        }
    }
}

// ---------------- projection RU -> U, RH ----------------
__global__ __launch_bounds__(256)
void proj_ru(const float* __restrict__ b_ru) {
    int m = blockIdx.x;
    __shared__ float Fs[64][32];
    __shared__ float Ws[32][128];
    int t = threadIdx.x;
    int nb = (t >> 5) * 8;
    int oc = (t & 31) * 4;
    float acc[8][4] = {};

    for (int ch = 0; ch < 12; ++ch) {
        int k0 = ch * 32;
        int s = k0 >> 6, f0 = k0 & 63;
        const float* base;
        switch (s) {
            case 0: base = g_XH; break; case 1: base = g_A1; break; case 2: base = g_A2; break;
            case 3: base = g_XH; break; case 4: base = g_A1; break; default: base = g_A2; break;
        }
        const float* src = base + (size_t)m * CXH + (s >= 3 ? C1 : 0) + f0;
        __syncthreads();
        for (int q = t; q < 512; q += 256) {
            int node = q >> 3, j4 = (q & 7) * 4;
            *(float4*)&Fs[node][j4] = *(const float4*)(src + node * 64 + j4);
        }
        for (int q = t; q < 1024; q += 256) {
            int row = q >> 5, c4 = (q & 31) * 4;
            *(float4*)&Ws[row][c4] = *(const float4*)&g_Wru[(k0 + row) * 128 + c4];
        }
        __syncthreads();
        #pragma unroll
        for (int kk = 0; kk < 32; ++kk) {
            float4 w = *(float4*)&Ws[kk][oc];
            #pragma unroll
            for (int i = 0; i < 8; ++i) {
                float fv = Fs[nb + i][kk];
                acc[i][0] += fv * w.x; acc[i][1] += fv * w.y;
                acc[i][2] += fv * w.z; acc[i][3] += fv * w.w;
            }
        }
    }
    float bias[4] = {b_ru[oc], b_ru[oc + 1], b_ru[oc + 2], b_ru[oc + 3]};
    #pragma unroll
    for (int i = 0; i < 8; ++i) {
        int b = nb + i;
        #pragma unroll
        for (int j = 0; j < 4; ++j) {
            int o = oc + j;
            float v = 1.0f / (1.0f + expf(-(acc[i][j] + bias[j])));
            if (o < 64) {
                float h = g_XH[(size_t)m * CXH + C1 + b * 64 + o];
                g_RH[(size_t)m * C1 + b * 64 + o] = v * h;
            } else {
                g_U[(size_t)m * C1 + b * 64 + (o - 64)] = v;
            }
        }
    }
}

// ---------------- projection C + GRU combine ----------------
__global__ __launch_bounds__(256)
void proj_c(const float* __restrict__ b_c, float* __restrict__ out) {
    int m = blockIdx.x;
    __shared__ float Fs[64][32];
    __shared__ float Ws[32][64];
    int t = threadIdx.x;
    int nb = (t >> 5) * 8;
    int oc = (t & 31) * 2;
    float acc[8][2] = {};

    for (int ch = 0; ch < 12; ++ch) {
        int k0 = ch * 32;
        int s = k0 >> 6, f0 = k0 & 63;
        const float* src;
        switch (s) {
            case 0: src = g_XH  + (size_t)m * CXH; break;
            case 1: src = g_A1  + (size_t)m * CXH; break;
            case 2: src = g_A2  + (size_t)m * CXH; break;
            case 3: src = g_RH  + (size_t)m * C1;  break;
            case 4: src = g_AR1 + (size_t)m * C1;  break;
            default: src = g_AR2 + (size_t)m * C1; break;
        }
        src += f0;
        __syncthreads();
        for (int q = t; q < 512; q += 256) {
            int node = q >> 3, j4 = (q & 7) * 4;
            *(float4*)&Fs[node][j4] = *(const float4*)(src + node * 64 + j4);
        }
        for (int q = t; q < 512; q += 256) {
            int row = q >> 4, c4 = (q & 15) * 4;
            *(float4*)&Ws[row][c4] = *(const float4*)&g_Wc[(k0 + row) * 64 + c4];
        }
        __syncthreads();
        #pragma unroll
        for (int kk = 0; kk < 32; ++kk) {
            float2 w = *(float2*)&Ws[kk][oc];
            #pragma unroll
            for (int i = 0; i < 8; ++i) {
                float fv = Fs[nb + i][kk];
                acc[i][0] += fv * w.x; acc[i][1] += fv * w.y;
            }
        }
    }
    float bias[2] = {b_c[oc], b_c[oc + 1]};
    #pragma unroll
    for (int i = 0; i < 8; ++i) {
        int b = nb + i;
        #pragma unroll
        for (int j = 0; j < 2; ++j) {
            int o = oc + j;
            float c = tanhf(acc[i][j] + bias[j]);
            float u = g_U[(size_t)m * C1 + b * 64 + o];
            float h = g_XH[(size_t)m * CXH + C1 + b * 64 + o];
            out[(size_t)b * (NN * 64) + m * 64 + o] = u * h + (1.0f - u) * c;
        }
    }
}

// ---------------- launch ----------------
extern "C" void kernel_launch(void* const* d_in, const int* in_sizes, int n_in,
                              void* d_out, int out_size) {
    const float* inputs = (const float*)d_in[0];
    const float* hx     = (const float*)d_in[1];
    const float* adj    = (const float*)d_in[2];
    const float* W_ru   = (const float*)d_in[3];
    const float* b_ru   = (const float*)d_in[4];
    const float* W_c    = (const float*)d_in[5];
    const float* b_c    = (const float*)d_in[6];
    float* out = (float*)d_out;

    float *p_XH, *p_A1, *p_A2, *p_RH, *p_AR1, *p_AR2;
    __nv_bfloat16 *p_Asp, *p_B1, *p_B2, *p_B3, *p_B4;
    cudaGetSymbolAddress((void**)&p_XH,  g_XH);
    cudaGetSymbolAddress((void**)&p_A1,  g_A1);
    cudaGetSymbolAddress((void**)&p_A2,  g_A2);
    cudaGetSymbolAddress((void**)&p_RH,  g_RH);
    cudaGetSymbolAddress((void**)&p_AR1, g_AR1);
    cudaGetSymbolAddress((void**)&p_AR2, g_AR2);
    cudaGetSymbolAddress((void**)&p_Asp, g_Asp);
    cudaGetSymbolAddress((void**)&p_B1,  g_B1);
    cudaGetSymbolAddress((void**)&p_B2,  g_B2);
    cudaGetSymbolAddress((void**)&p_B3,  g_B3);
    cudaGetSymbolAddress((void**)&p_B4,  g_B4);

    cudaFuncSetAttribute(gemm_mma, cudaFuncAttributeMaxDynamicSharedMemorySize, GSMEM);

    rowsum_kernel<<<NN, 256>>>(adj);
    pack_XH<<<(NN * CXH / 4) / 256, 256>>>(inputs, hx);
    permW<<<(384 * 128 + 255) / 256, 256>>>(W_ru, W_c);
    buildA_split<<<dim3(32, 32), 256>>>(adj);

    // A1 = adjT @ XH
    split_T<<<dim3(CXH / 64, 32), 256>>>(p_XH, p_B1, CXH);
    gemm_mma<<<dim3(CXH / 256, 16), 512, GSMEM>>>(p_Asp, p_B1, nullptr, p_A1, CXH, 1.0f, 0.0f);
    // A2 = 2*adjT@A1 - XH
    split_T<<<dim3(CXH / 64, 32), 256>>>(p_A1, p_B2, CXH);
    gemm_mma<<<dim3(CXH / 256, 16), 512, GSMEM>>>(p_Asp, p_B2, p_XH, p_A2, CXH, 2.0f, -1.0f);

    proj_ru<<<NN, 256>>>(b_ru);

    // AR1 = adjT @ RH ; AR2 = 2*adjT@AR1 - RH
    split_T<<<dim3(C1 / 64, 32), 256>>>(p_RH, p_B3, C1);
    gemm_mma<<<dim3(C1 / 256, 16), 512, GSMEM>>>(p_Asp, p_B3, nullptr, p_AR1, C1, 1.0f, 0.0f);
    split_T<<<dim3(C1 / 64, 32), 256>>>(p_AR1, p_B4, C1);
    gemm_mma<<<dim3(C1 / 256, 16), 512, GSMEM>>>(p_Asp, p_B4, p_RH, p_AR2, C1, 2.0f, -1.0f);

    proj_c<<<NN, 256>>>(b_c, out);
}

// round 6
// speedup vs baseline: 4.7956x; 1.8870x over previous
#include <cuda_runtime.h>
#include <cuda_fp16.h>
#include <math.h>
#include <stdint.h>

#define NN 2048      // nodes
#define CXH 8192     // 2*64*64 columns of [x|h]
#define C1  4096     // 64*64
#define KD  2048     // GEMM K (fp16 1-term)

// ---------------- device scratch ----------------
__device__ float g_dinv[NN];
__device__ float g_XH [(size_t)NN * CXH];
__device__ float g_A1 [(size_t)NN * CXH];
__device__ float g_A2 [(size_t)NN * CXH];
__device__ float g_RH [(size_t)NN * C1];
__device__ float g_AR1[(size_t)NN * C1];
__device__ float g_AR2[(size_t)NN * C1];
__device__ float g_U  [(size_t)NN * C1];
__device__ float g_Wru[384 * 128];
__device__ float g_Wc [384 * 64];
__device__ __half g_Ah[(size_t)NN * KD];     // fp16 adjT, [m][k]
__device__ __half g_Bh[(size_t)CXH * KD];    // fp16 B operand [c][k] (reused)

// ---------------- helpers ----------------
__device__ __forceinline__ uint32_t smem_u32(const void* p) {
    uint32_t a;
    asm("{ .reg .u64 t; cvta.to.shared.u64 t, %1; cvt.u32.u64 %0, t; }" : "=r"(a) : "l"(p));
    return a;
}
__device__ __forceinline__ void cpasync16(uint32_t dst, const void* src) {
    asm volatile("cp.async.cg.shared.global [%0], [%1], 16;" :: "r"(dst), "l"(src));
}
__device__ __forceinline__ void ldsm4(uint32_t* r, uint32_t addr) {
    asm volatile("ldmatrix.sync.aligned.m8n8.x4.shared.b16 {%0,%1,%2,%3}, [%4];"
        : "=r"(r[0]), "=r"(r[1]), "=r"(r[2]), "=r"(r[3]) : "r"(addr));
}
__device__ __forceinline__ void mma16816(float* d, const uint32_t* a, const uint32_t* b) {
    asm volatile("mma.sync.aligned.m16n8k16.row.col.f32.f16.f16.f32 "
        "{%0,%1,%2,%3}, {%4,%5,%6,%7}, {%8,%9}, {%0,%1,%2,%3};"
        : "+f"(d[0]), "+f"(d[1]), "+f"(d[2]), "+f"(d[3])
        : "r"(a[0]), "r"(a[1]), "r"(a[2]), "r"(a[3]), "r"(b[0]), "r"(b[1]));
}

// ---------------- launch 1: row sums ----------------
__global__ void rowsum_kernel(const float* __restrict__ adj) {
    int m = blockIdx.x;
    const float* row = adj + (size_t)m * NN;
    float s = 0.f;
    for (int i = threadIdx.x; i < NN; i += 256) s += row[i];
    #pragma unroll
    for (int o = 16; o; o >>= 1) s += __shfl_down_sync(0xffffffffu, s, o);
    __shared__ float sm[8];
    if ((threadIdx.x & 31) == 0) sm[threadIdx.x >> 5] = s;
    __syncthreads();
    if (threadIdx.x < 8) {
        float v = sm[threadIdx.x];
        #pragma unroll
        for (int o = 4; o; o >>= 1) v += __shfl_down_sync(0xffu, v, o);
        if (threadIdx.x == 0) g_dinv[m] = 1.0f / (v + 1.0f);
    }
}

// ---------------- launch 2: pack XH + permute W (fused) ----------------
__global__ void pack_permW(const float* __restrict__ x, const float* __restrict__ h,
                           const float* __restrict__ Wru, const float* __restrict__ Wc) {
    int bid = blockIdx.x;
    int t = threadIdx.x;
    if (bid < 16384) {
        int idx4 = bid * 256 + t;
        int m = idx4 >> 11;
        int c = (idx4 & 2047) * 4;
        const float* src;
        if (c < C1) { int b = c >> 6, f = c & 63; src = x + (size_t)b * (NN * 64) + m * 64 + f; }
        else { int cc = c - C1; int b = cc >> 6, f = cc & 63; src = h + (size_t)b * (NN * 64) + m * 64 + f; }
        *(float4*)&g_XH[(size_t)m * CXH + c] = *(const float4*)src;
    } else {
        int tid = (bid - 16384) * 256 + t;
        if (tid < 384 * 128) {
            int row = tid >> 7, o = tid & 127;
            int s = row >> 6, f = row & 63;
            int src = (s < 3) ? (f * 3 + s) : (192 + f * 3 + (s - 3));
            g_Wru[row * 128 + o] = Wru[src * 128 + o];
        }
        if (tid < 384 * 64) {
            int row = tid >> 6, o = tid & 63;
            int s = row >> 6, f = row & 63;
            int src = (s < 3) ? (f * 3 + s) : (192 + f * 3 + (s - 3));
            g_Wc[row * 64 + o] = Wc[src * 64 + o];
        }
    }
}

// ---------------- launch 3: build fp16 adjT + fp16 transpose of XH (fused) ----------------
// part A (blocks 0..1023): g_Ah[m][k] = fp16((adj[k][m] + (k==m)) * dinv[k])
// part B (blocks 1024..5119): g_Bh[c][k] = fp16(g_XH[k][c])
__global__ void conv1(const float* __restrict__ adj) {
    __shared__ float tile[64][65];
    int bid = blockIdx.x;
    int t = threadIdx.x;
    if (bid < 1024) {
        __shared__ float sdinv[64];
        int k0 = (bid >> 5) * 64, m0 = (bid & 31) * 64;
        if (t < 64) sdinv[t] = g_dinv[k0 + t];
        #pragma unroll
        for (int i = 0; i < 16; i++) {
            int q = t + 256 * i; int r = q >> 6, c = q & 63;
            tile[r][c] = adj[(size_t)(k0 + r) * NN + m0 + c];
        }
        __syncthreads();
        #pragma unroll
        for (int i = 0; i < 16; i++) {
            int q = t + 256 * i; int f = q >> 6, n = q & 63;
            int kk = k0 + n, mm = m0 + f;
            float v = tile[n][f];
            if (kk == mm) v += 1.0f;
            g_Ah[(size_t)mm * KD + kk] = __float2half_rn(v * sdinv[n]);
        }
    } else {
        int tb = bid - 1024;                   // 4096 blocks
        int c0 = (tb & 127) * 64, k0 = (tb >> 7) * 64;
        #pragma unroll
        for (int i = 0; i < 16; i++) {
            int q = t + 256 * i; int r = q >> 6, c = q & 63;
            tile[r][c] = g_XH[(size_t)(k0 + r) * CXH + c0 + c];
        }
        __syncthreads();
        #pragma unroll
        for (int i = 0; i < 16; i++) {
            int q = t + 256 * i; int f = q >> 6, n = q & 63;
            g_Bh[(size_t)(c0 + f) * KD + (k0 + n)] = __float2half_rn(tile[n][f]);
        }
    }
}

// ---------------- fp16 transpose: g_Bh[c][k] = fp16(src[k][c]) ----------------
__global__ void trans_f16(const float* __restrict__ src, int Ncols) {
    __shared__ float tile[64][65];
    int k0 = blockIdx.y * 64, c0 = blockIdx.x * 64;
    int t = threadIdx.x;
    #pragma unroll
    for (int i = 0; i < 16; i++) {
        int q = t + 256 * i; int r = q >> 6, c = q & 63;
        tile[r][c] = src[(size_t)(k0 + r) * Ncols + c0 + c];
    }
    __syncthreads();
    #pragma unroll
    for (int i = 0; i < 16; i++) {
        int q = t + 256 * i; int f = q >> 6, n = q & 63;
        g_Bh[(size_t)(c0 + f) * KD + (k0 + n)] = __float2half_rn(tile[n][f]);
    }
}

// ---------------- HMMA GEMM: Cout = alpha*(A @ B^T) + beta*Cin ----------------
// A: [2048][KD] fp16 row-major; B: [Ncols][KD] fp16 row-major (k contiguous).
// CTA tile 128(M) x 256(N), BK=32, 512 threads (16 warps, warp tile 64x32).
#define ROWB 80
#define ASZ  (128 * ROWB)
#define BSZ  (256 * ROWB)
#define STB  (ASZ + BSZ)
#define GSMEM (4 * STB)
#define NST  (KD / 32)            // 64

__global__ __launch_bounds__(512, 1)
void gemm_mma(const __half* __restrict__ A, const __half* __restrict__ B,
              const float* __restrict__ Cin, float* __restrict__ Cout,
              int Ncols, float alpha, float beta) {
    extern __shared__ char smem[];
    uint32_t sbase = smem_u32(smem);
    int t = threadIdx.x;
    int lane = t & 31, wid = t >> 5;
    int m0 = blockIdx.y * 128;
    int n0 = blockIdx.x * 256;
    int wm = (wid & 1) * 64;
    int wn = (wid >> 1) * 32;

    uint32_t aOff[4], bOff[2];
    #pragma unroll
    for (int mt = 0; mt < 4; mt++)
        aOff[mt] = (uint32_t)((wm + mt * 16 + (lane & 15)) * ROWB + (lane >> 4) * 16);
    #pragma unroll
    for (int np = 0; np < 2; np++)
        bOff[np] = (uint32_t)(ASZ + (wn + np * 16 + (lane & 7) + ((lane >> 4) << 3)) * ROWB
                              + ((lane >> 3) & 1) * 16);

    auto load_stage = [&](int s) {
        int slot = s & 3; int k0 = s * 32;
        uint32_t ab = sbase + slot * STB;
        const __half* gA = A + (size_t)m0 * KD + k0;
        const __half* gB = B + (size_t)n0 * KD + k0;
        #pragma unroll
        for (int i = 0; i < 3; i++) {
            int q = t + 512 * i;
            if (q < 512) {
                int r = q >> 2, c4 = q & 3;
                cpasync16(ab + r * ROWB + c4 * 16, gA + (size_t)r * KD + c4 * 8);
            } else {
                int qq = q - 512; int r = qq >> 2, c4 = qq & 3;
                cpasync16(ab + ASZ + r * ROWB + c4 * 16, gB + (size_t)r * KD + c4 * 8);
            }
        }
        asm volatile("cp.async.commit_group;" ::: "memory");
    };

    float acc[4][4][4] = {};

    load_stage(0); load_stage(1); load_stage(2);

    for (int s = 0; s < NST; ++s) {
        if (s <= NST - 3)      asm volatile("cp.async.wait_group 2;" ::: "memory");
        else if (s == NST - 2) asm volatile("cp.async.wait_group 1;" ::: "memory");
        else                   asm volatile("cp.async.wait_group 0;" ::: "memory");
        __syncthreads();

        uint32_t sb = sbase + (s & 3) * STB;
        #pragma unroll
        for (int k16 = 0; k16 < 2; k16++) {
            uint32_t a[4][4], b[2][4];
            #pragma unroll
            for (int mt = 0; mt < 4; mt++) ldsm4(a[mt], sb + aOff[mt] + k16 * 32);
            #pragma unroll
            for (int np = 0; np < 2; np++) ldsm4(b[np], sb + bOff[np] + k16 * 32);
            #pragma unroll
            for (int mt = 0; mt < 4; mt++)
                #pragma unroll
                for (int nt = 0; nt < 4; nt++)
                    mma16816(acc[mt][nt], a[mt], &b[nt >> 1][(nt & 1) * 2]);
        }

        if (s + 3 < NST) load_stage(s + 3);
    }

    bool has_cin = (Cin != nullptr);
    #pragma unroll
    for (int mt = 0; mt < 4; mt++) {
        #pragma unroll
        for (int nt = 0; nt < 4; nt++) {
            int m = m0 + wm + mt * 16 + (lane >> 2);
            int n = n0 + wn + nt * 8 + (lane & 3) * 2;
            size_t g0 = (size_t)m * Ncols + n;
            size_t g1 = g0 + (size_t)8 * Ncols;
            float v0 = alpha * acc[mt][nt][0], v1 = alpha * acc[mt][nt][1];
            float v2 = alpha * acc[mt][nt][2], v3 = alpha * acc[mt][nt][3];
            if (has_cin) {
                float2 c0 = *(const float2*)&Cin[g0];
                float2 c1 = *(const float2*)&Cin[g1];
                v0 += beta * c0.x; v1 += beta * c0.y;
                v2 += beta * c1.x; v3 += beta * c1.y;
            }
            float2 o0 = {v0, v1}, o1 = {v2, v3};
            *(float2*)&Cout[g0] = o0;
            *(float2*)&Cout[g1] = o1;
        }
    }
}

// ---------------- projection RU -> U, RH ----------------
__global__ __launch_bounds__(256)
void proj_ru(const float* __restrict__ b_ru) {
    int m = blockIdx.x;
    __shared__ float Fs[64][32];
    __shared__ float Ws[32][128];
    int t = threadIdx.x;
    int nb = (t >> 5) * 8;
    int oc = (t & 31) * 4;
    float acc[8][4] = {};

    for (int ch = 0; ch < 12; ++ch) {
        int k0 = ch * 32;
        int s = k0 >> 6, f0 = k0 & 63;
        const float* base;
        switch (s) {
            case 0: base = g_XH; break; case 1: base = g_A1; break; case 2: base = g_A2; break;
            case 3: base = g_XH; break; case 4: base = g_A1; break; default: base = g_A2; break;
        }
        const float* src = base + (size_t)m * CXH + (s >= 3 ? C1 : 0) + f0;
        __syncthreads();
        for (int q = t; q < 512; q += 256) {
            int node = q >> 3, j4 = (q & 7) * 4;
            *(float4*)&Fs[node][j4] = *(const float4*)(src + node * 64 + j4);
        }
        for (int q = t; q < 1024; q += 256) {
            int row = q >> 5, c4 = (q & 31) * 4;
            *(float4*)&Ws[row][c4] = *(const float4*)&g_Wru[(k0 + row) * 128 + c4];
        }
        __syncthreads();
        #pragma unroll
        for (int kk = 0; kk < 32; ++kk) {
            float4 w = *(float4*)&Ws[kk][oc];
            #pragma unroll
            for (int i = 0; i < 8; ++i) {
                float fv = Fs[nb + i][kk];
                acc[i][0] += fv * w.x; acc[i][1] += fv * w.y;
                acc[i][2] += fv * w.z; acc[i][3] += fv * w.w;
            }
        }
    }
    float bias[4] = {b_ru[oc], b_ru[oc + 1], b_ru[oc + 2], b_ru[oc + 3]};
    #pragma unroll
    for (int i = 0; i < 8; ++i) {
        int b = nb + i;
        #pragma unroll
        for (int j = 0; j < 4; ++j) {
            int o = oc + j;
            float v = 1.0f / (1.0f + expf(-(acc[i][j] + bias[j])));
            if (o < 64) {
                float h = g_XH[(size_t)m * CXH + C1 + b * 64 + o];
                g_RH[(size_t)m * C1 + b * 64 + o] = v * h;
            } else {
                g_U[(size_t)m * C1 + b * 64 + (o - 64)] = v;
            }
        }
    }
}

// ---------------- projection C + GRU combine ----------------
__global__ __launch_bounds__(256)
void proj_c(const float* __restrict__ b_c, float* __restrict__ out) {
    int m = blockIdx.x;
    __shared__ float Fs[64][32];
    __shared__ float Ws[32][64];
    int t = threadIdx.x;
    int nb = (t >> 5) * 8;
    int oc = (t & 31) * 2;
    float acc[8][2] = {};

    for (int ch = 0; ch < 12; ++ch) {
        int k0 = ch * 32;
        int s = k0 >> 6, f0 = k0 & 63;
        const float* src;
        switch (s) {
            case 0: src = g_XH  + (size_t)m * CXH; break;
            case 1: src = g_A1  + (size_t)m * CXH; break;
            case 2: src = g_A2  + (size_t)m * CXH; break;
            case 3: src = g_RH  + (size_t)m * C1;  break;
            case 4: src = g_AR1 + (size_t)m * C1;  break;
            default: src = g_AR2 + (size_t)m * C1; break;
        }
        src += f0;
        __syncthreads();
        for (int q = t; q < 512; q += 256) {
            int node = q >> 3, j4 = (q & 7) * 4;
            *(float4*)&Fs[node][j4] = *(const float4*)(src + node * 64 + j4);
        }
        for (int q = t; q < 512; q += 256) {
            int row = q >> 4, c4 = (q & 15) * 4;
            *(float4*)&Ws[row][c4] = *(const float4*)&g_Wc[(k0 + row) * 64 + c4];
        }
        __syncthreads();
        #pragma unroll
        for (int kk = 0; kk < 32; ++kk) {
            float2 w = *(float2*)&Ws[kk][oc];
            #pragma unroll
            for (int i = 0; i < 8; ++i) {
                float fv = Fs[nb + i][kk];
                acc[i][0] += fv * w.x; acc[i][1] += fv * w.y;
            }
        }
    }
    float bias[2] = {b_c[oc], b_c[oc + 1]};
    #pragma unroll
    for (int i = 0; i < 8; ++i) {
        int b = nb + i;
        #pragma unroll
        for (int j = 0; j < 2; ++j) {
            int o = oc + j;
            float c = tanhf(acc[i][j] + bias[j]);
            float u = g_U[(size_t)m * C1 + b * 64 + o];
            float h = g_XH[(size_t)m * CXH + C1 + b * 64 + o];
            out[(size_t)b * (NN * 64) + m * 64 + o] = u * h + (1.0f - u) * c;
        }
    }
}

// ---------------- launch ----------------
extern "C" void kernel_launch(void* const* d_in, const int* in_sizes, int n_in,
                              void* d_out, int out_size) {
    const float* inputs = (const float*)d_in[0];
    const float* hx     = (const float*)d_in[1];
    const float* adj    = (const float*)d_in[2];
    const float* W_ru   = (const float*)d_in[3];
    const float* b_ru   = (const float*)d_in[4];
    const float* W_c    = (const float*)d_in[5];
    const float* b_c    = (const float*)d_in[6];
    float* out = (float*)d_out;

    float *p_XH, *p_A1, *p_A2, *p_RH, *p_AR1, *p_AR2;
    __half *p_Ah, *p_Bh;
    cudaGetSymbolAddress((void**)&p_XH,  g_XH);
    cudaGetSymbolAddress((void**)&p_A1,  g_A1);
    cudaGetSymbolAddress((void**)&p_A2,  g_A2);
    cudaGetSymbolAddress((void**)&p_RH,  g_RH);
    cudaGetSymbolAddress((void**)&p_AR1, g_AR1);
    cudaGetSymbolAddress((void**)&p_AR2, g_AR2);
    cudaGetSymbolAddress((void**)&p_Ah,  g_Ah);
    cudaGetSymbolAddress((void**)&p_Bh,  g_Bh);

    cudaFuncSetAttribute(gemm_mma, cudaFuncAttributeMaxDynamicSharedMemorySize, GSMEM);

    rowsum_kernel<<<NN, 256>>>(adj);                       // 1
    pack_permW<<<16384 + 192, 256>>>(inputs, hx, W_ru, W_c); // 2
    conv1<<<1024 + 4096, 256>>>(adj);                      // 3: fp16 adjT + fp16 XH^T

    // 4: A1 = adjT @ XH   (profiled launch)
    gemm_mma<<<dim3(CXH / 256, 16), 512, GSMEM>>>(p_Ah, p_Bh, nullptr, p_A1, CXH, 1.0f, 0.0f);
    // A2 = 2*adjT@A1 - XH
    trans_f16<<<dim3(CXH / 64, 32), 256>>>(p_A1, CXH);
    gemm_mma<<<dim3(CXH / 256, 16), 512, GSMEM>>>(p_Ah, p_Bh, p_XH, p_A2, CXH, 2.0f, -1.0f);

    proj_ru<<<NN, 256>>>(b_ru);

    // AR1 = adjT @ RH ; AR2 = 2*adjT@AR1 - RH
    trans_f16<<<dim3(C1 / 64, 32), 256>>>(p_RH, C1);
    gemm_mma<<<dim3(C1 / 256, 16), 512, GSMEM>>>(p_Ah, p_Bh, nullptr, p_AR1, C1, 1.0f, 0.0f);
    trans_f16<<<dim3(C1 / 64, 32), 256>>>(p_AR1, C1);
    gemm_mma<<<dim3(C1 / 256, 16), 512, GSMEM>>>(p_Ah, p_Bh, p_RH, p_AR2, C1, 2.0f, -1.0f);

    proj_c<<<NN, 256>>>(b_c, out);
}

// round 7
// speedup vs baseline: 6.0429x; 1.2601x over previous
#include <cuda_runtime.h>
#include <cuda_fp16.h>
#include <math.h>
#include <stdint.h>

#define NN 2048      // nodes
#define CXH 8192     // 2*64*64 columns of [x|h]
#define C1  4096     // 64*64
#define KD  2048     // GEMM K (fp16 1-term)
#define FSTR 392     // padded half-stride for projection smem rows (384+8)

// ---------------- device scratch ----------------
__device__ float g_dinv[NN];
__device__ float g_XH [(size_t)NN * CXH];
__device__ float g_A1 [(size_t)NN * CXH];
__device__ float g_A2 [(size_t)NN * CXH];
__device__ float g_RH [(size_t)NN * C1];
__device__ float g_AR1[(size_t)NN * C1];
__device__ float g_AR2[(size_t)NN * C1];
__device__ float g_U  [(size_t)NN * C1];
__device__ __half g_Wruh[128 * 384];         // fp16, [n][k], k = s*64+f permuted
__device__ __half g_Wch [64 * 384];
__device__ __half g_Ah[(size_t)NN * KD];     // fp16 adjT, [m][k]
__device__ __half g_Bh[(size_t)CXH * KD];    // fp16 B operand [c][k] (reused)

// ---------------- helpers ----------------
__device__ __forceinline__ uint32_t smem_u32(const void* p) {
    uint32_t a;
    asm("{ .reg .u64 t; cvta.to.shared.u64 t, %1; cvt.u32.u64 %0, t; }" : "=r"(a) : "l"(p));
    return a;
}
__device__ __forceinline__ void cpasync16(uint32_t dst, const void* src) {
    asm volatile("cp.async.cg.shared.global [%0], [%1], 16;" :: "r"(dst), "l"(src));
}
__device__ __forceinline__ void ldsm4(uint32_t* r, uint32_t addr) {
    asm volatile("ldmatrix.sync.aligned.m8n8.x4.shared.b16 {%0,%1,%2,%3}, [%4];"
        : "=r"(r[0]), "=r"(r[1]), "=r"(r[2]), "=r"(r[3]) : "r"(addr));
}
__device__ __forceinline__ void mma16816(float* d, const uint32_t* a, const uint32_t* b) {
    asm volatile("mma.sync.aligned.m16n8k16.row.col.f32.f16.f16.f32 "
        "{%0,%1,%2,%3}, {%4,%5,%6,%7}, {%8,%9}, {%0,%1,%2,%3};"
        : "+f"(d[0]), "+f"(d[1]), "+f"(d[2]), "+f"(d[3])
        : "r"(a[0]), "r"(a[1]), "r"(a[2]), "r"(a[3]), "r"(b[0]), "r"(b[1]));
}
__device__ __forceinline__ int wsrc_row(int k) {
    int s = k >> 6, f = k & 63;
    return (s < 3) ? (f * 3 + s) : (192 + f * 3 + (s - 3));
}

// ---------------- launch 1: row sums ----------------
__global__ void rowsum_kernel(const float* __restrict__ adj) {
    int m = blockIdx.x;
    const float* row = adj + (size_t)m * NN;
    float s = 0.f;
    for (int i = threadIdx.x; i < NN; i += 256) s += row[i];
    #pragma unroll
    for (int o = 16; o; o >>= 1) s += __shfl_down_sync(0xffffffffu, s, o);
    __shared__ float sm[8];
    if ((threadIdx.x & 31) == 0) sm[threadIdx.x >> 5] = s;
    __syncthreads();
    if (threadIdx.x < 8) {
        float v = sm[threadIdx.x];
        #pragma unroll
        for (int o = 4; o; o >>= 1) v += __shfl_down_sync(0xffu, v, o);
        if (threadIdx.x == 0) g_dinv[m] = 1.0f / (v + 1.0f);
    }
}

// ---------------- launch 2: pack XH + build fp16 transposed weights ----------------
__global__ void pack_permW(const float* __restrict__ x, const float* __restrict__ h,
                           const float* __restrict__ Wru, const float* __restrict__ Wc) {
    int bid = blockIdx.x;
    int t = threadIdx.x;
    if (bid < 16384) {
        int idx4 = bid * 256 + t;
        int m = idx4 >> 11;
        int c = (idx4 & 2047) * 4;
        const float* src;
        if (c < C1) { int b = c >> 6, f = c & 63; src = x + (size_t)b * (NN * 64) + m * 64 + f; }
        else { int cc = c - C1; int b = cc >> 6, f = cc & 63; src = h + (size_t)b * (NN * 64) + m * 64 + f; }
        *(float4*)&g_XH[(size_t)m * CXH + c] = *(const float4*)src;
    } else {
        int idx = (bid - 16384) * 256 + t;
        if (idx < 128 * 384) {
            int n = idx / 384, k = idx % 384;
            g_Wruh[n * 384 + k] = __float2half_rn(Wru[wsrc_row(k) * 128 + n]);
        } else if (idx < 128 * 384 + 64 * 384) {
            int j = idx - 128 * 384;
            int n = j / 384, k = j % 384;
            g_Wch[n * 384 + k] = __float2half_rn(Wc[wsrc_row(k) * 64 + n]);
        }
    }
}

// ---------------- launch 3: build fp16 adjT + fp16 transpose of XH (fused) ----------------
__global__ void conv1(const float* __restrict__ adj) {
    __shared__ float tile[64][65];
    int bid = blockIdx.x;
    int t = threadIdx.x;
    if (bid < 1024) {
        __shared__ float sdinv[64];
        int k0 = (bid >> 5) * 64, m0 = (bid & 31) * 64;
        if (t < 64) sdinv[t] = g_dinv[k0 + t];
        #pragma unroll
        for (int i = 0; i < 16; i++) {
            int q = t + 256 * i; int r = q >> 6, c = q & 63;
            tile[r][c] = adj[(size_t)(k0 + r) * NN + m0 + c];
        }
        __syncthreads();
        #pragma unroll
        for (int i = 0; i < 16; i++) {
            int q = t + 256 * i; int f = q >> 6, n = q & 63;
            int kk = k0 + n, mm = m0 + f;
            float v = tile[n][f];
            if (kk == mm) v += 1.0f;
            g_Ah[(size_t)mm * KD + kk] = __float2half_rn(v * sdinv[n]);
        }
    } else {
        int tb = bid - 1024;                   // 4096 blocks
        int c0 = (tb & 127) * 64, k0 = (tb >> 7) * 64;
        #pragma unroll
        for (int i = 0; i < 16; i++) {
            int q = t + 256 * i; int r = q >> 6, c = q & 63;
            tile[r][c] = g_XH[(size_t)(k0 + r) * CXH + c0 + c];
        }
        __syncthreads();
        #pragma unroll
        for (int i = 0; i < 16; i++) {
            int q = t + 256 * i; int f = q >> 6, n = q & 63;
            g_Bh[(size_t)(c0 + f) * KD + (k0 + n)] = __float2half_rn(tile[n][f]);
        }
    }
}

// ---------------- fp16 transpose: g_Bh[c][k] = fp16(src[k][c]) ----------------
__global__ void trans_f16(const float* __restrict__ src, int Ncols) {
    __shared__ float tile[64][65];
    int k0 = blockIdx.y * 64, c0 = blockIdx.x * 64;
    int t = threadIdx.x;
    #pragma unroll
    for (int i = 0; i < 16; i++) {
        int q = t + 256 * i; int r = q >> 6, c = q & 63;
        tile[r][c] = src[(size_t)(k0 + r) * Ncols + c0 + c];
    }
    __syncthreads();
    #pragma unroll
    for (int i = 0; i < 16; i++) {
        int q = t + 256 * i; int f = q >> 6, n = q & 63;
        g_Bh[(size_t)(c0 + f) * KD + (k0 + n)] = __float2half_rn(tile[n][f]);
    }
}

// ---------------- HMMA GEMM: Cout = alpha*(A @ B^T) + beta*Cin ----------------
#define ROWB 80
#define ASZ  (128 * ROWB)
#define BSZ  (256 * ROWB)
#define STB  (ASZ + BSZ)
#define GSMEM (4 * STB)
#define NST  (KD / 32)            // 64

__global__ __launch_bounds__(512, 1)
void gemm_mma(const __half* __restrict__ A, const __half* __restrict__ B,
              const float* __restrict__ Cin, float* __restrict__ Cout,
              int Ncols, float alpha, float beta) {
    extern __shared__ char smem[];
    uint32_t sbase = smem_u32(smem);
    int t = threadIdx.x;
    int lane = t & 31, wid = t >> 5;
    int m0 = blockIdx.y * 128;
    int n0 = blockIdx.x * 256;
    int wm = (wid & 1) * 64;
    int wn = (wid >> 1) * 32;

    uint32_t aOff[4], bOff[2];
    #pragma unroll
    for (int mt = 0; mt < 4; mt++)
        aOff[mt] = (uint32_t)((wm + mt * 16 + (lane & 15)) * ROWB + (lane >> 4) * 16);
    #pragma unroll
    for (int np = 0; np < 2; np++)
        bOff[np] = (uint32_t)(ASZ + (wn + np * 16 + (lane & 7) + ((lane >> 4) << 3)) * ROWB
                              + ((lane >> 3) & 1) * 16);

    auto load_stage = [&](int s) {
        int slot = s & 3; int k0 = s * 32;
        uint32_t ab = sbase + slot * STB;
        const __half* gA = A + (size_t)m0 * KD + k0;
        const __half* gB = B + (size_t)n0 * KD + k0;
        #pragma unroll
        for (int i = 0; i < 3; i++) {
            int q = t + 512 * i;
            if (q < 512) {
                int r = q >> 2, c4 = q & 3;
                cpasync16(ab + r * ROWB + c4 * 16, gA + (size_t)r * KD + c4 * 8);
            } else {
                int qq = q - 512; int r = qq >> 2, c4 = qq & 3;
                cpasync16(ab + ASZ + r * ROWB + c4 * 16, gB + (size_t)r * KD + c4 * 8);
            }
        }
        asm volatile("cp.async.commit_group;" ::: "memory");
    };

    float acc[4][4][4] = {};

    load_stage(0); load_stage(1); load_stage(2);

    for (int s = 0; s < NST; ++s) {
        if (s <= NST - 3)      asm volatile("cp.async.wait_group 2;" ::: "memory");
        else if (s == NST - 2) asm volatile("cp.async.wait_group 1;" ::: "memory");
        else                   asm volatile("cp.async.wait_group 0;" ::: "memory");
        __syncthreads();

        uint32_t sb = sbase + (s & 3) * STB;
        #pragma unroll
        for (int k16 = 0; k16 < 2; k16++) {
            uint32_t a[4][4], b[2][4];
            #pragma unroll
            for (int mt = 0; mt < 4; mt++) ldsm4(a[mt], sb + aOff[mt] + k16 * 32);
            #pragma unroll
            for (int np = 0; np < 2; np++) ldsm4(b[np], sb + bOff[np] + k16 * 32);
            #pragma unroll
            for (int mt = 0; mt < 4; mt++)
                #pragma unroll
                for (int nt = 0; nt < 4; nt++)
                    mma16816(acc[mt][nt], a[mt], &b[nt >> 1][(nt & 1) * 2]);
        }

        if (s + 3 < NST) load_stage(s + 3);
    }

    bool has_cin = (Cin != nullptr);
    #pragma unroll
    for (int mt = 0; mt < 4; mt++) {
        #pragma unroll
        for (int nt = 0; nt < 4; nt++) {
            int m = m0 + wm + mt * 16 + (lane >> 2);
            int n = n0 + wn + nt * 8 + (lane & 3) * 2;
            size_t g0 = (size_t)m * Ncols + n;
            size_t g1 = g0 + (size_t)8 * Ncols;
            float v0 = alpha * acc[mt][nt][0], v1 = alpha * acc[mt][nt][1];
            float v2 = alpha * acc[mt][nt][2], v3 = alpha * acc[mt][nt][3];
            if (has_cin) {
                float2 c0 = *(const float2*)&Cin[g0];
                float2 c1 = *(const float2*)&Cin[g1];
                v0 += beta * c0.x; v1 += beta * c0.y;
                v2 += beta * c1.x; v3 += beta * c1.y;
            }
            float2 o0 = {v0, v1}, o1 = {v2, v3};
            *(float2*)&Cout[g0] = o0;
            *(float2*)&Cout[g1] = o1;
        }
    }
}

// ---------------- HMMA projection RU: 64x128, K=384 per node ----------------
#define PRU_SMEM ((64 + 128) * FSTR * 2)
__global__ __launch_bounds__(128)
void proj_ru_mma(const float* __restrict__ b_ru) {
    extern __shared__ char ps[];
    __half* Fs = (__half*)ps;                         // [64][FSTR]
    __half* Ws = (__half*)(ps + 64 * FSTR * 2);       // [128][FSTR]
    uint32_t fsb = smem_u32(Fs), wsb = smem_u32(Ws);
    int m = blockIdx.x, t = threadIdx.x;
    int lane = t & 31, wid = t >> 5;
    int wm = (wid & 1) * 32, wn = (wid >> 1) * 64;

    const float* seg[6] = {
        g_XH + (size_t)m * CXH,      g_A1 + (size_t)m * CXH,      g_A2 + (size_t)m * CXH,
        g_XH + (size_t)m * CXH + C1, g_A1 + (size_t)m * CXH + C1, g_A2 + (size_t)m * CXH + C1 };
    #pragma unroll
    for (int s = 0; s < 6; s++) {
        #pragma unroll
        for (int i = 0; i < 8; i++) {
            int q = t + 128 * i;               // 1024 float4 per segment
            int b = q >> 4, f4 = (q & 15) * 4;
            float4 v = *(const float4*)(seg[s] + b * 64 + f4);
            __half2* dst = (__half2*)(Fs + b * FSTR + s * 64 + f4);
            dst[0] = __floats2half2_rn(v.x, v.y);
            dst[1] = __floats2half2_rn(v.z, v.w);
        }
    }
    for (int q = t; q < 128 * 48; q += 128) {  // 16B chunks of W
        int n = q / 48, c = q % 48;
        *(uint4*)(Ws + n * FSTR + c * 8) = *(const uint4*)(g_Wruh + n * 384 + c * 8);
    }
    __syncthreads();

    uint32_t aOff[2], bOff[4];
    #pragma unroll
    for (int mt = 0; mt < 2; mt++)
        aOff[mt] = fsb + (wm + mt * 16 + (lane & 15)) * (FSTR * 2) + (lane >> 4) * 16;
    #pragma unroll
    for (int np = 0; np < 4; np++)
        bOff[np] = wsb + (wn + np * 16 + (lane & 7) + ((lane >> 4) << 3)) * (FSTR * 2)
                   + ((lane >> 3) & 1) * 16;

    float acc[2][8][4] = {};
    #pragma unroll
    for (int k = 0; k < 24; k++) {
        uint32_t a[2][4], b[4][4];
        #pragma unroll
        for (int mt = 0; mt < 2; mt++) ldsm4(a[mt], aOff[mt] + k * 32);
        #pragma unroll
        for (int np = 0; np < 4; np++) ldsm4(b[np], bOff[np] + k * 32);
        #pragma unroll
        for (int mt = 0; mt < 2; mt++)
            #pragma unroll
            for (int nt = 0; nt < 8; nt++)
                mma16816(acc[mt][nt], a[mt], &b[nt >> 1][(nt & 1) * 2]);
    }

    #pragma unroll
    for (int mt = 0; mt < 2; mt++) {
        #pragma unroll
        for (int nt = 0; nt < 8; nt++) {
            int brow = wm + mt * 16 + (lane >> 2);
            int o = wn + nt * 8 + (lane & 3) * 2;
            float bo0 = b_ru[o], bo1 = b_ru[o + 1];
            #pragma unroll
            for (int half_i = 0; half_i < 2; half_i++) {
                int b = brow + half_i * 8;
                float v0 = 1.0f / (1.0f + expf(-(acc[mt][nt][half_i * 2 + 0] + bo0)));
                float v1 = 1.0f / (1.0f + expf(-(acc[mt][nt][half_i * 2 + 1] + bo1)));
                if (o < 64) {
                    float h0 = g_XH[(size_t)m * CXH + C1 + b * 64 + o];
                    float h1 = g_XH[(size_t)m * CXH + C1 + b * 64 + o + 1];
                    g_RH[(size_t)m * C1 + b * 64 + o]     = v0 * h0;
                    g_RH[(size_t)m * C1 + b * 64 + o + 1] = v1 * h1;
                } else {
                    g_U[(size_t)m * C1 + b * 64 + (o - 64)]     = v0;
                    g_U[(size_t)m * C1 + b * 64 + (o - 64) + 1] = v1;
                }
            }
        }
    }
}

// ---------------- HMMA projection C + GRU combine: 64x64, K=384 per node ----------------
#define PC_SMEM ((64 + 64) * FSTR * 2)
__global__ __launch_bounds__(128)
void proj_c_mma(const float* __restrict__ b_c, float* __restrict__ out) {
    extern __shared__ char ps[];
    __half* Fs = (__half*)ps;                         // [64][FSTR]
    __half* Ws = (__half*)(ps + 64 * FSTR * 2);       // [64][FSTR]
    uint32_t fsb = smem_u32(Fs), wsb = smem_u32(Ws);
    int m = blockIdx.x, t = threadIdx.x;
    int lane = t & 31, wid = t >> 5;
    int wm = (wid & 1) * 32, wn = (wid >> 1) * 32;

    const float* seg[6] = {
        g_XH + (size_t)m * CXH, g_A1 + (size_t)m * CXH, g_A2 + (size_t)m * CXH,
        g_RH + (size_t)m * C1,  g_AR1 + (size_t)m * C1, g_AR2 + (size_t)m * C1 };
    #pragma unroll
    for (int s = 0; s < 6; s++) {
        #pragma unroll
        for (int i = 0; i < 8; i++) {
            int q = t + 128 * i;
            int b = q >> 4, f4 = (q & 15) * 4;
            float4 v = *(const float4*)(seg[s] + b * 64 + f4);
            __half2* dst = (__half2*)(Fs + b * FSTR + s * 64 + f4);
            dst[0] = __floats2half2_rn(v.x, v.y);
            dst[1] = __floats2half2_rn(v.z, v.w);
        }
    }
    for (int q = t; q < 64 * 48; q += 128) {
        int n = q / 48, c = q % 48;
        *(uint4*)(Ws + n * FSTR + c * 8) = *(const uint4*)(g_Wch + n * 384 + c * 8);
    }
    __syncthreads();

    uint32_t aOff[2], bOff[2];
    #pragma unroll
    for (int mt = 0; mt < 2; mt++)
        aOff[mt] = fsb + (wm + mt * 16 + (lane & 15)) * (FSTR * 2) + (lane >> 4) * 16;
    #pragma unroll
    for (int np = 0; np < 2; np++)
        bOff[np] = wsb + (wn + np * 16 + (lane & 7) + ((lane >> 4) << 3)) * (FSTR * 2)
                   + ((lane >> 3) & 1) * 16;

    float acc[2][4][4] = {};
    #pragma unroll
    for (int k = 0; k < 24; k++) {
        uint32_t a[2][4], b[2][4];
        #pragma unroll
        for (int mt = 0; mt < 2; mt++) ldsm4(a[mt], aOff[mt] + k * 32);
        #pragma unroll
        for (int np = 0; np < 2; np++) ldsm4(b[np], bOff[np] + k * 32);
        #pragma unroll
        for (int mt = 0; mt < 2; mt++)
            #pragma unroll
            for (int nt = 0; nt < 4; nt++)
                mma16816(acc[mt][nt], a[mt], &b[nt >> 1][(nt & 1) * 2]);
    }

    #pragma unroll
    for (int mt = 0; mt < 2; mt++) {
        #pragma unroll
        for (int nt = 0; nt < 4; nt++) {
            int brow = wm + mt * 16 + (lane >> 2);
            int o = wn + nt * 8 + (lane & 3) * 2;
            float bo0 = b_c[o], bo1 = b_c[o + 1];
            #pragma unroll
            for (int half_i = 0; half_i < 2; half_i++) {
                int b = brow + half_i * 8;
                float c0 = tanhf(acc[mt][nt][half_i * 2 + 0] + bo0);
                float c1 = tanhf(acc[mt][nt][half_i * 2 + 1] + bo1);
                float u0 = g_U[(size_t)m * C1 + b * 64 + o];
                float u1 = g_U[(size_t)m * C1 + b * 64 + o + 1];
                float h0 = g_XH[(size_t)m * CXH + C1 + b * 64 + o];
                float h1 = g_XH[(size_t)m * CXH + C1 + b * 64 + o + 1];
                float2 ov = {u0 * h0 + (1.0f - u0) * c0, u1 * h1 + (1.0f - u1) * c1};
                *(float2*)&out[(size_t)b * (NN * 64) + m * 64 + o] = ov;
            }
        }
    }
}

// ---------------- launch ----------------
extern "C" void kernel_launch(void* const* d_in, const int* in_sizes, int n_in,
                              void* d_out, int out_size) {
    const float* inputs = (const float*)d_in[0];
    const float* hx     = (const float*)d_in[1];
    const float* adj    = (const float*)d_in[2];
    const float* W_ru   = (const float*)d_in[3];
    const float* b_ru   = (const float*)d_in[4];
    const float* W_c    = (const float*)d_in[5];
    const float* b_c    = (const float*)d_in[6];
    float* out = (float*)d_out;

    float *p_XH, *p_A1, *p_A2, *p_RH, *p_AR1, *p_AR2;
    __half *p_Ah, *p_Bh;
    cudaGetSymbolAddress((void**)&p_XH,  g_XH);
    cudaGetSymbolAddress((void**)&p_A1,  g_A1);
    cudaGetSymbolAddress((void**)&p_A2,  g_A2);
    cudaGetSymbolAddress((void**)&p_RH,  g_RH);
    cudaGetSymbolAddress((void**)&p_AR1, g_AR1);
    cudaGetSymbolAddress((void**)&p_AR2, g_AR2);
    cudaGetSymbolAddress((void**)&p_Ah,  g_Ah);
    cudaGetSymbolAddress((void**)&p_Bh,  g_Bh);

    cudaFuncSetAttribute(gemm_mma,    cudaFuncAttributeMaxDynamicSharedMemorySize, GSMEM);
    cudaFuncSetAttribute(proj_ru_mma, cudaFuncAttributeMaxDynamicSharedMemorySize, PRU_SMEM);
    cudaFuncSetAttribute(proj_c_mma,  cudaFuncAttributeMaxDynamicSharedMemorySize, PC_SMEM);

    rowsum_kernel<<<NN, 256>>>(adj);                         // 1
    pack_permW<<<16384 + 288, 256>>>(inputs, hx, W_ru, W_c); // 2
    conv1<<<1024 + 4096, 256>>>(adj);                        // 3

    // 4: A1 = adjT @ XH   (profiled launch)
    gemm_mma<<<dim3(CXH / 256, 16), 512, GSMEM>>>(p_Ah, p_Bh, nullptr, p_A1, CXH, 1.0f, 0.0f);
    // A2 = 2*adjT@A1 - XH
    trans_f16<<<dim3(CXH / 64, 32), 256>>>(p_A1, CXH);
    gemm_mma<<<dim3(CXH / 256, 16), 512, GSMEM>>>(p_Ah, p_Bh, p_XH, p_A2, CXH, 2.0f, -1.0f);

    proj_ru_mma<<<NN, 128, PRU_SMEM>>>(b_ru);

    // AR1 = adjT @ RH ; AR2 = 2*adjT@AR1 - RH
    trans_f16<<<dim3(C1 / 64, 32), 256>>>(p_RH, C1);
    gemm_mma<<<dim3(C1 / 256, 16), 512, GSMEM>>>(p_Ah, p_Bh, nullptr, p_AR1, C1, 1.0f, 0.0f);
    trans_f16<<<dim3(C1 / 64, 32), 256>>>(p_AR1, C1);
    gemm_mma<<<dim3(C1 / 256, 16), 512, GSMEM>>>(p_Ah, p_Bh, p_RH, p_AR2, C1, 2.0f, -1.0f);

    proj_c_mma<<<NN, 128, PC_SMEM>>>(b_c, out);
}